// round 5
// baseline (speedup 1.0000x reference)
#include <cuda_runtime.h>
#include <math.h>

// Problem constants (fixed shapes from reference)
#define BATCH  8
#define C_IN   256
#define NPIX   1024   // 32*32
#define INNER  512    // heads*dim_head
#define HEADS  8
#define DH     64
#define KCONV  2304   // 256*9
#define MKV    1024   // 2*INNER

// Scratch (static device globals — no allocation allowed)
__device__ float g_Q [(size_t)BATCH * INNER * NPIX];   // [b][h*64+d][p]
__device__ float g_KV[(size_t)BATCH * MKV   * NPIX];   // [b][co][p], co<512: K, co>=512: V
__device__ float g_AO[(size_t)BATCH * INNER * NPIX];   // gelu(attention out), [b][h*64+d][p]

// ---------------------------------------------------------------------------
// Generic tiled GEMM for 1x1 convs:
//   C[z][m][n] = sum_k A[m][k] * B[z][k][n]  (+ bias[m])
// Tile 64x64, BK=16, 256 threads, 4x4 per thread.
// ---------------------------------------------------------------------------
template<int BIAS>
__global__ __launch_bounds__(256)
void gemm_1x1(const float* __restrict__ A, const float* __restrict__ Bm,
              float* __restrict__ Cm, const float* __restrict__ bias,
              int M, int N, int K)
{
    __shared__ float sA[16][65];
    __shared__ float sB[16][65];
    const int t  = threadIdx.x;
    const int tx = t & 15, ty = t >> 4;
    const int n0 = blockIdx.x * 64, m0 = blockIdx.y * 64;
    const float* Bp = Bm + (size_t)blockIdx.z * K * N;
    float*       Cp = Cm + (size_t)blockIdx.z * M * N;

    float acc[4][4] = {};
    for (int k0 = 0; k0 < K; k0 += 16) {
        #pragma unroll
        for (int r = 0; r < 4; r++) {
            int idx = t + r * 256;
            { int kk = idx & 15, m = idx >> 4;
              sA[kk][m] = A[(size_t)(m0 + m) * K + k0 + kk]; }
            { int nn = idx & 63, kk = idx >> 6;
              sB[kk][nn] = Bp[(size_t)(k0 + kk) * N + n0 + nn]; }
        }
        __syncthreads();
        #pragma unroll
        for (int kk = 0; kk < 16; kk++) {
            float a[4], b[4];
            #pragma unroll
            for (int i = 0; i < 4; i++) a[i] = sA[kk][ty * 4 + i];
            #pragma unroll
            for (int j = 0; j < 4; j++) b[j] = sB[kk][tx * 4 + j];
            #pragma unroll
            for (int i = 0; i < 4; i++)
                #pragma unroll
                for (int j = 0; j < 4; j++)
                    acc[i][j] = fmaf(a[i], b[j], acc[i][j]);
        }
        __syncthreads();
    }
    #pragma unroll
    for (int i = 0; i < 4; i++) {
        int m = m0 + ty * 4 + i;
        float bv = BIAS ? bias[m] : 0.f;
        #pragma unroll
        for (int j = 0; j < 4; j++)
            Cp[(size_t)m * N + n0 + tx * 4 + j] = acc[i][j] + bv;
    }
}

// ---------------------------------------------------------------------------
// 3x3 conv (pad=1) as implicit GEMM:
//   KV[b][co][p] = sum_{k=ci*9+tap} W[co][k] * X[b][ci][shift_tap(p)]
// M=1024, N=1024, K=2304. Same 64x64 tile scheme; B-tile load does the
// im2col gather with boundary predication.
// ---------------------------------------------------------------------------
__global__ __launch_bounds__(256)
void conv3x3_kv(const float* __restrict__ W, const float* __restrict__ X)
{
    __shared__ float sA[16][65];
    __shared__ float sB[16][65];
    const int t  = threadIdx.x;
    const int tx = t & 15, ty = t >> 4;
    const int n0 = blockIdx.x * 64, m0 = blockIdx.y * 64;
    const float* Xp = X    + (size_t)blockIdx.z * C_IN * NPIX;
    float*       Cp = g_KV + (size_t)blockIdx.z * MKV  * NPIX;

    float acc[4][4] = {};
    for (int k0 = 0; k0 < KCONV; k0 += 16) {
        #pragma unroll
        for (int r = 0; r < 4; r++) {
            int idx = t + r * 256;
            { int kk = idx & 15, m = idx >> 4;
              sA[kk][m] = W[(size_t)(m0 + m) * KCONV + k0 + kk]; }
            { int nn = idx & 63, kk = idx >> 6;
              int kg  = k0 + kk;
              int ci  = kg / 9;
              int tap = kg - ci * 9;
              int dy  = tap / 3 - 1;
              int dx  = tap - (tap / 3) * 3 - 1;
              int n   = n0 + nn;
              int y   = (n >> 5) + dy;
              int x   = (n & 31) + dx;
              float v = 0.f;
              if ((unsigned)y < 32u && (unsigned)x < 32u)
                  v = Xp[(size_t)ci * NPIX + (y << 5) + x];
              sB[kk][nn] = v; }
        }
        __syncthreads();
        #pragma unroll
        for (int kk = 0; kk < 16; kk++) {
            float a[4], b[4];
            #pragma unroll
            for (int i = 0; i < 4; i++) a[i] = sA[kk][ty * 4 + i];
            #pragma unroll
            for (int j = 0; j < 4; j++) b[j] = sB[kk][tx * 4 + j];
            #pragma unroll
            for (int i = 0; i < 4; i++)
                #pragma unroll
                for (int j = 0; j < 4; j++)
                    acc[i][j] = fmaf(a[i], b[j], acc[i][j]);
        }
        __syncthreads();
    }
    #pragma unroll
    for (int i = 0; i < 4; i++) {
        int m = m0 + ty * 4 + i;
        #pragma unroll
        for (int j = 0; j < 4; j++)
            Cp[(size_t)m * NPIX + n0 + tx * 4 + j] = acc[i][j];
    }
}

// ---------------------------------------------------------------------------
// Flash attention (fp32, exact): one CTA per (b*h, 64-query tile).
// n=1024 keys, d=64. Online softmax, O accumulator in registers (4x4/thread).
// GELU (exact, erf) fused into epilogue; coalesced writeback via smem stage.
// ---------------------------------------------------------------------------
#define FA_SMEM_FLOATS (4 * 64 * 65 + 3 * 64)

__global__ __launch_bounds__(256)
void flash_attn(const float* __restrict__ Q, const float* __restrict__ KV,
                float* __restrict__ AO)
{
    extern __shared__ float sm[];
    float* sQ = sm;               // [64][65]
    float* sK = sQ + 64 * 65;     // [64][65]
    float* sV = sK + 64 * 65;     // [64][65]
    float* sS = sV + 64 * 65;     // [64][65]
    float* rm = sS + 64 * 65;     // [64] running max
    float* rl = rm + 64;          // [64] running denom
    float* rf = rl + 64;          // [64] rescale factor

    const int t  = threadIdx.x;
    const int tx = t & 15, ty = t >> 4;
    const int q0 = blockIdx.x * 64;
    const int bh = blockIdx.y;
    const int b  = bh >> 3, h = bh & 7;

    const float* qb = Q  + ((size_t)b * INNER + h * DH) * NPIX;
    const float* kb = KV + ((size_t)b * MKV   + h * DH) * NPIX;
    const float* vb = KV + ((size_t)b * MKV + INNER + h * DH) * NPIX;
    float*       ob = AO + ((size_t)b * INNER + h * DH) * NPIX;

    // Load Q tile: sQ[qi][d]  (coalesced over p, conflict-free stride-65 store)
    for (int idx = t; idx < 4096; idx += 256) {
        int d = idx >> 6, qi = idx & 63;
        sQ[qi * 65 + d] = qb[(size_t)d * NPIX + q0 + qi];
    }
    if (t < 64) { rm[t] = -1e30f; rl[t] = 0.f; }

    float O[4][4] = {};
    const float scale = 0.125f;  // 64^-0.5

    for (int k0 = 0; k0 < NPIX; k0 += 64) {
        for (int idx = t; idx < 4096; idx += 256) {
            int d = idx >> 6, ki = idx & 63;
            sK[ki * 65 + d] = kb[(size_t)d * NPIX + k0 + ki];
            sV[ki * 65 + d] = vb[(size_t)d * NPIX + k0 + ki];
        }
        __syncthreads();

        // S = scale * Q K^T  (64x64 tile, regs)
        float s[4][4] = {};
        #pragma unroll 8
        for (int d = 0; d < 64; d++) {
            float a[4], k[4];
            #pragma unroll
            for (int i = 0; i < 4; i++) a[i] = sQ[(ty * 4 + i) * 65 + d];
            #pragma unroll
            for (int j = 0; j < 4; j++) k[j] = sK[(tx * 4 + j) * 65 + d];
            #pragma unroll
            for (int i = 0; i < 4; i++)
                #pragma unroll
                for (int j = 0; j < 4; j++)
                    s[i][j] = fmaf(a[i], k[j], s[i][j]);
        }
        #pragma unroll
        for (int i = 0; i < 4; i++)
            #pragma unroll
            for (int j = 0; j < 4; j++)
                sS[(ty * 4 + i) * 65 + tx * 4 + j] = s[i][j] * scale;
        __syncthreads();

        // Online softmax: thread r handles row r (r < 64)
        if (t < 64) {
            float mo = rm[t];
            float mx = mo;
            #pragma unroll 8
            for (int j = 0; j < 64; j++) mx = fmaxf(mx, sS[t * 65 + j]);
            float sum = 0.f;
            #pragma unroll 8
            for (int j = 0; j < 64; j++) {
                float e = expf(sS[t * 65 + j] - mx);
                sS[t * 65 + j] = e;
                sum += e;
            }
            float f = expf(mo - mx);
            rf[t] = f;
            rl[t] = rl[t] * f + sum;
            rm[t] = mx;
        }
        __syncthreads();

        // Rescale O, then O += P V
        #pragma unroll
        for (int i = 0; i < 4; i++) {
            float f = rf[ty * 4 + i];
            #pragma unroll
            for (int j = 0; j < 4; j++) O[i][j] *= f;
        }
        #pragma unroll 8
        for (int kk = 0; kk < 64; kk++) {
            float p[4], v[4];
            #pragma unroll
            for (int i = 0; i < 4; i++) p[i] = sS[(ty * 4 + i) * 65 + kk];
            #pragma unroll
            for (int j = 0; j < 4; j++) v[j] = sV[kk * 65 + tx * 4 + j];
            #pragma unroll
            for (int i = 0; i < 4; i++)
                #pragma unroll
                for (int j = 0; j < 4; j++)
                    O[i][j] = fmaf(p[i], v[j], O[i][j]);
        }
        __syncthreads();
    }

    // Epilogue: normalize, exact GELU, stage in smem, coalesced writeback
    #pragma unroll
    for (int i = 0; i < 4; i++) {
        float inv = 1.f / rl[ty * 4 + i];
        #pragma unroll
        for (int j = 0; j < 4; j++) {
            float v = O[i][j] * inv;
            float g = 0.5f * v * (1.f + erff(v * 0.70710678118654752f));
            sS[(ty * 4 + i) * 65 + tx * 4 + j] = g;
        }
    }
    __syncthreads();
    for (int idx = t; idx < 4096; idx += 256) {
        int d = idx >> 6, qi = idx & 63;
        ob[(size_t)d * NPIX + q0 + qi] = sS[qi * 65 + d];
    }
}

// ---------------------------------------------------------------------------
extern "C" void kernel_launch(void* const* d_in, const int* in_sizes, int n_in,
                              void* d_out, int out_size)
{
    const float* x    = (const float*)d_in[0];  // [8,256,32,32]
    const float* Wq   = (const float*)d_in[1];  // [512,256,1,1]
    const float* Wkv  = (const float*)d_in[2];  // [1024,256,3,3]
    const float* Wout = (const float*)d_in[3];  // [256,512,1,1]
    const float* bout = (const float*)d_in[4];  // [256]
    float* out = (float*)d_out;                 // [8,256,32,32]

    float *qp, *kvp, *aop;
    cudaGetSymbolAddress((void**)&qp,  g_Q);
    cudaGetSymbolAddress((void**)&kvp, g_KV);
    cudaGetSymbolAddress((void**)&aop, g_AO);

    dim3 blk(256);

    // 1) Q = Wq * x        (M=512, N=1024, K=256, per batch)
    gemm_1x1<0><<<dim3(NPIX / 64, INNER / 64, BATCH), blk>>>(
        Wq, x, qp, nullptr, INNER, NPIX, C_IN);

    // 2) KV = conv3x3(x)   (M=1024, N=1024, K=2304, per batch)
    conv3x3_kv<<<dim3(NPIX / 64, MKV / 64, BATCH), blk>>>(Wkv, x);

    // 3) Flash attention + GELU fused
    int smem = FA_SMEM_FLOATS * (int)sizeof(float);  // 67328 B
    cudaFuncSetAttribute(flash_attn,
                         cudaFuncAttributeMaxDynamicSharedMemorySize, smem);
    flash_attn<<<dim3(NPIX / 64, BATCH * HEADS), blk, smem>>>(qp, kvp, aop);

    // 4) out = Wout * gelu_attn + bout   (M=256, N=1024, K=512, per batch)
    gemm_1x1<1><<<dim3(NPIX / 64, 256 / 64, BATCH), blk>>>(
        Wout, aop, out, bout, 256, NPIX, INNER);
}

// round 6
// speedup vs baseline: 1.0017x; 1.0017x over previous
#include <cuda_runtime.h>
#include <math.h>

// Problem constants (fixed shapes from reference)
#define BATCH  8
#define C_IN   256
#define NPIX   1024   // 32*32
#define INNER  512    // heads*dim_head
#define HEADS  8
#define DH     64
#define KCONV  2304   // 256*9
#define MKV    1024   // 2*INNER

// Scratch (static device globals — no allocation allowed)
__device__ float g_Q [(size_t)BATCH * INNER * NPIX];   // [b][h*64+d][p]
__device__ float g_KV[(size_t)BATCH * MKV   * NPIX];   // [b][co][p], co<512: K, co>=512: V
__device__ float g_AO[(size_t)BATCH * INNER * NPIX];   // gelu(attention out), [b][h*64+d][p]

// ---------------------------------------------------------------------------
// Generic tiled GEMM for 1x1 convs:
//   C[z][m][n] = sum_k A[m][k] * B[z][k][n]  (+ bias[m])
// Tile 64x64, BK=16, 256 threads, 4x4 per thread.
// ---------------------------------------------------------------------------
template<int BIAS>
__global__ __launch_bounds__(256)
void gemm_1x1(const float* __restrict__ A, const float* __restrict__ Bm,
              float* __restrict__ Cm, const float* __restrict__ bias,
              int M, int N, int K)
{
    __shared__ float sA[16][65];
    __shared__ float sB[16][65];
    const int t  = threadIdx.x;
    const int tx = t & 15, ty = t >> 4;
    const int n0 = blockIdx.x * 64, m0 = blockIdx.y * 64;
    const float* Bp = Bm + (size_t)blockIdx.z * K * N;
    float*       Cp = Cm + (size_t)blockIdx.z * M * N;

    float acc[4][4] = {};
    for (int k0 = 0; k0 < K; k0 += 16) {
        #pragma unroll
        for (int r = 0; r < 4; r++) {
            int idx = t + r * 256;
            { int kk = idx & 15, m = idx >> 4;
              sA[kk][m] = A[(size_t)(m0 + m) * K + k0 + kk]; }
            { int nn = idx & 63, kk = idx >> 6;
              sB[kk][nn] = Bp[(size_t)(k0 + kk) * N + n0 + nn]; }
        }
        __syncthreads();
        #pragma unroll
        for (int kk = 0; kk < 16; kk++) {
            float a[4], b[4];
            #pragma unroll
            for (int i = 0; i < 4; i++) a[i] = sA[kk][ty * 4 + i];
            #pragma unroll
            for (int j = 0; j < 4; j++) b[j] = sB[kk][tx * 4 + j];
            #pragma unroll
            for (int i = 0; i < 4; i++)
                #pragma unroll
                for (int j = 0; j < 4; j++)
                    acc[i][j] = fmaf(a[i], b[j], acc[i][j]);
        }
        __syncthreads();
    }
    #pragma unroll
    for (int i = 0; i < 4; i++) {
        int m = m0 + ty * 4 + i;
        float bv = BIAS ? bias[m] : 0.f;
        #pragma unroll
        for (int j = 0; j < 4; j++)
            Cp[(size_t)m * N + n0 + tx * 4 + j] = acc[i][j] + bv;
    }
}

// ---------------------------------------------------------------------------
// 3x3 conv (pad=1) as implicit GEMM:
//   KV[b][co][p] = sum_{k=ci*9+tap} W[co][k] * X[b][ci][shift_tap(p)]
// M=1024, N=1024, K=2304. Same 64x64 tile scheme; B-tile load does the
// im2col gather with boundary predication.
// ---------------------------------------------------------------------------
__global__ __launch_bounds__(256)
void conv3x3_kv(const float* __restrict__ W, const float* __restrict__ X)
{
    __shared__ float sA[16][65];
    __shared__ float sB[16][65];
    const int t  = threadIdx.x;
    const int tx = t & 15, ty = t >> 4;
    const int n0 = blockIdx.x * 64, m0 = blockIdx.y * 64;
    const float* Xp = X    + (size_t)blockIdx.z * C_IN * NPIX;
    float*       Cp = g_KV + (size_t)blockIdx.z * MKV  * NPIX;

    float acc[4][4] = {};
    for (int k0 = 0; k0 < KCONV; k0 += 16) {
        #pragma unroll
        for (int r = 0; r < 4; r++) {
            int idx = t + r * 256;
            { int kk = idx & 15, m = idx >> 4;
              sA[kk][m] = W[(size_t)(m0 + m) * KCONV + k0 + kk]; }
            { int nn = idx & 63, kk = idx >> 6;
              int kg  = k0 + kk;
              int ci  = kg / 9;
              int tap = kg - ci * 9;
              int dy  = tap / 3 - 1;
              int dx  = tap - (tap / 3) * 3 - 1;
              int n   = n0 + nn;
              int y   = (n >> 5) + dy;
              int x   = (n & 31) + dx;
              float v = 0.f;
              if ((unsigned)y < 32u && (unsigned)x < 32u)
                  v = Xp[(size_t)ci * NPIX + (y << 5) + x];
              sB[kk][nn] = v; }
        }
        __syncthreads();
        #pragma unroll
        for (int kk = 0; kk < 16; kk++) {
            float a[4], b[4];
            #pragma unroll
            for (int i = 0; i < 4; i++) a[i] = sA[kk][ty * 4 + i];
            #pragma unroll
            for (int j = 0; j < 4; j++) b[j] = sB[kk][tx * 4 + j];
            #pragma unroll
            for (int i = 0; i < 4; i++)
                #pragma unroll
                for (int j = 0; j < 4; j++)
                    acc[i][j] = fmaf(a[i], b[j], acc[i][j]);
        }
        __syncthreads();
    }
    #pragma unroll
    for (int i = 0; i < 4; i++) {
        int m = m0 + ty * 4 + i;
        #pragma unroll
        for (int j = 0; j < 4; j++)
            Cp[(size_t)m * NPIX + n0 + tx * 4 + j] = acc[i][j];
    }
}

// ---------------------------------------------------------------------------
// Flash attention (fp32, exact): one CTA per (b*h, 64-query tile).
// n=1024 keys, d=64. Online softmax, O accumulator in registers (4x4/thread).
// GELU (exact, erf) fused into epilogue; coalesced writeback via smem stage.
// ---------------------------------------------------------------------------
#define FA_SMEM_FLOATS (4 * 64 * 65 + 3 * 64)

__global__ __launch_bounds__(256)
void flash_attn(const float* __restrict__ Q, const float* __restrict__ KV,
                float* __restrict__ AO)
{
    extern __shared__ float sm[];
    float* sQ = sm;               // [64][65]
    float* sK = sQ + 64 * 65;     // [64][65]
    float* sV = sK + 64 * 65;     // [64][65]
    float* sS = sV + 64 * 65;     // [64][65]
    float* rm = sS + 64 * 65;     // [64] running max
    float* rl = rm + 64;          // [64] running denom
    float* rf = rl + 64;          // [64] rescale factor

    const int t  = threadIdx.x;
    const int tx = t & 15, ty = t >> 4;
    const int q0 = blockIdx.x * 64;
    const int bh = blockIdx.y;
    const int b  = bh >> 3, h = bh & 7;

    const float* qb = Q  + ((size_t)b * INNER + h * DH) * NPIX;
    const float* kb = KV + ((size_t)b * MKV   + h * DH) * NPIX;
    const float* vb = KV + ((size_t)b * MKV + INNER + h * DH) * NPIX;
    float*       ob = AO + ((size_t)b * INNER + h * DH) * NPIX;

    // Load Q tile: sQ[qi][d]  (coalesced over p, conflict-free stride-65 store)
    for (int idx = t; idx < 4096; idx += 256) {
        int d = idx >> 6, qi = idx & 63;
        sQ[qi * 65 + d] = qb[(size_t)d * NPIX + q0 + qi];
    }
    if (t < 64) { rm[t] = -1e30f; rl[t] = 0.f; }

    float O[4][4] = {};
    const float scale = 0.125f;  // 64^-0.5

    for (int k0 = 0; k0 < NPIX; k0 += 64) {
        for (int idx = t; idx < 4096; idx += 256) {
            int d = idx >> 6, ki = idx & 63;
            sK[ki * 65 + d] = kb[(size_t)d * NPIX + k0 + ki];
            sV[ki * 65 + d] = vb[(size_t)d * NPIX + k0 + ki];
        }
        __syncthreads();

        // S = scale * Q K^T  (64x64 tile, regs)
        float s[4][4] = {};
        #pragma unroll 8
        for (int d = 0; d < 64; d++) {
            float a[4], k[4];
            #pragma unroll
            for (int i = 0; i < 4; i++) a[i] = sQ[(ty * 4 + i) * 65 + d];
            #pragma unroll
            for (int j = 0; j < 4; j++) k[j] = sK[(tx * 4 + j) * 65 + d];
            #pragma unroll
            for (int i = 0; i < 4; i++)
                #pragma unroll
                for (int j = 0; j < 4; j++)
                    s[i][j] = fmaf(a[i], k[j], s[i][j]);
        }
        #pragma unroll
        for (int i = 0; i < 4; i++)
            #pragma unroll
            for (int j = 0; j < 4; j++)
                sS[(ty * 4 + i) * 65 + tx * 4 + j] = s[i][j] * scale;
        __syncthreads();

        // Online softmax: thread r handles row r (r < 64)
        if (t < 64) {
            float mo = rm[t];
            float mx = mo;
            #pragma unroll 8
            for (int j = 0; j < 64; j++) mx = fmaxf(mx, sS[t * 65 + j]);
            float sum = 0.f;
            #pragma unroll 8
            for (int j = 0; j < 64; j++) {
                float e = expf(sS[t * 65 + j] - mx);
                sS[t * 65 + j] = e;
                sum += e;
            }
            float f = expf(mo - mx);
            rf[t] = f;
            rl[t] = rl[t] * f + sum;
            rm[t] = mx;
        }
        __syncthreads();

        // Rescale O, then O += P V
        #pragma unroll
        for (int i = 0; i < 4; i++) {
            float f = rf[ty * 4 + i];
            #pragma unroll
            for (int j = 0; j < 4; j++) O[i][j] *= f;
        }
        #pragma unroll 8
        for (int kk = 0; kk < 64; kk++) {
            float p[4], v[4];
            #pragma unroll
            for (int i = 0; i < 4; i++) p[i] = sS[(ty * 4 + i) * 65 + kk];
            #pragma unroll
            for (int j = 0; j < 4; j++) v[j] = sV[kk * 65 + tx * 4 + j];
            #pragma unroll
            for (int i = 0; i < 4; i++)
                #pragma unroll
                for (int j = 0; j < 4; j++)
                    O[i][j] = fmaf(p[i], v[j], O[i][j]);
        }
        __syncthreads();
    }

    // Epilogue: normalize, exact GELU, stage in smem, coalesced writeback
    #pragma unroll
    for (int i = 0; i < 4; i++) {
        float inv = 1.f / rl[ty * 4 + i];
        #pragma unroll
        for (int j = 0; j < 4; j++) {
            float v = O[i][j] * inv;
            float g = 0.5f * v * (1.f + erff(v * 0.70710678118654752f));
            sS[(ty * 4 + i) * 65 + tx * 4 + j] = g;
        }
    }
    __syncthreads();
    for (int idx = t; idx < 4096; idx += 256) {
        int d = idx >> 6, qi = idx & 63;
        ob[(size_t)d * NPIX + q0 + qi] = sS[qi * 65 + d];
    }
}

// ---------------------------------------------------------------------------
extern "C" void kernel_launch(void* const* d_in, const int* in_sizes, int n_in,
                              void* d_out, int out_size)
{
    const float* x    = (const float*)d_in[0];  // [8,256,32,32]
    const float* Wq   = (const float*)d_in[1];  // [512,256,1,1]
    const float* Wkv  = (const float*)d_in[2];  // [1024,256,3,3]
    const float* Wout = (const float*)d_in[3];  // [256,512,1,1]
    const float* bout = (const float*)d_in[4];  // [256]
    float* out = (float*)d_out;                 // [8,256,32,32]

    float *qp, *kvp, *aop;
    cudaGetSymbolAddress((void**)&qp,  g_Q);
    cudaGetSymbolAddress((void**)&kvp, g_KV);
    cudaGetSymbolAddress((void**)&aop, g_AO);

    dim3 blk(256);

    // 1) Q = Wq * x        (M=512, N=1024, K=256, per batch)
    gemm_1x1<0><<<dim3(NPIX / 64, INNER / 64, BATCH), blk>>>(
        Wq, x, qp, nullptr, INNER, NPIX, C_IN);

    // 2) KV = conv3x3(x)   (M=1024, N=1024, K=2304, per batch)
    conv3x3_kv<<<dim3(NPIX / 64, MKV / 64, BATCH), blk>>>(Wkv, x);

    // 3) Flash attention + GELU fused
    int smem = FA_SMEM_FLOATS * (int)sizeof(float);  // 67328 B
    cudaFuncSetAttribute(flash_attn,
                         cudaFuncAttributeMaxDynamicSharedMemorySize, smem);
    flash_attn<<<dim3(NPIX / 64, BATCH * HEADS), blk, smem>>>(qp, kvp, aop);

    // 4) out = Wout * gelu_attn + bout   (M=256, N=1024, K=512, per batch)
    gemm_1x1<1><<<dim3(NPIX / 64, 256 / 64, BATCH), blk>>>(
        Wout, aop, out, bout, 256, NPIX, INNER);
}